// round 10
// baseline (speedup 1.0000x reference)
#include <cuda_runtime.h>
#include <cuda_bf16.h>
#include <cstdint>

#define N_SEQ 512
#define N_RES 384
#define C_M   256
#define C_OUTER 32
#define C_Z   128
#define M_DIM 12288                       // N_RES * C_OUTER
#define PLANE ((size_t)M_DIM * N_SEQ)     // elements per hi/lo plane

typedef unsigned long long ull;

// ---------------------------------------------------------------------
// Global scratch (allocation-free __device__ arrays)
// g_A/g_B: [2 planes (hi,lo)][m = b*32+c (12288)][a (512)] bf16, K-major.
// ---------------------------------------------------------------------
__device__ __nv_bfloat16 g_A[2 * M_DIM * N_SEQ];   // left^T  (24MB)
__device__ __nv_bfloat16 g_B[2 * M_DIM * N_SEQ];   // right^T (24MB)
__device__ float g_norm[N_RES * N_RES];

// ---------------- packed fp32x2 helpers ----------------
__device__ __forceinline__ ull pack2(float x, float y) {
    ull r; asm("mov.b64 %0, {%1, %2};" : "=l"(r) : "f"(x), "f"(y)); return r;
}
__device__ __forceinline__ void fma2(ull& d, ull a, ull b) {
    asm("fma.rn.f32x2 %0, %1, %2, %3;" : "=l"(d) : "l"(a), "l"(b), "l"(d));
}
__device__ __forceinline__ float lo2(ull v) { return __uint_as_float((unsigned)v); }
__device__ __forceinline__ float hi2(ull v) { return __uint_as_float((unsigned)(v >> 32)); }

// ---------------- smem / async-copy / mma helpers ----------------
__device__ __forceinline__ uint32_t smem_u32(const void* p) {
    uint32_t a;
    asm("{ .reg .u64 t; cvta.to.shared.u64 t, %1; cvt.u32.u64 %0, t; }" : "=r"(a) : "l"(p));
    return a;
}
__device__ __forceinline__ void cp16(uint32_t s, const void* g) {
    asm volatile("cp.async.cg.shared.global [%0], [%1], 16;" :: "r"(s), "l"(g));
}
#define CP_COMMIT() asm volatile("cp.async.commit_group;" ::: "memory")
#define CP_WAIT(n)  asm volatile("cp.async.wait_group %0;" :: "n"(n) : "memory")

#define LDSM4(r, addr) \
    asm volatile("ldmatrix.sync.aligned.m8n8.x4.shared.b16 {%0,%1,%2,%3}, [%4];" \
        : "=r"((r)[0]), "=r"((r)[1]), "=r"((r)[2]), "=r"((r)[3]) : "r"(addr))

__device__ __forceinline__ void mma16816(float* c, const uint32_t* a,
                                         uint32_t b0, uint32_t b1) {
    asm volatile("mma.sync.aligned.m16n8k16.row.col.f32.bf16.bf16.f32 "
                 "{%0,%1,%2,%3}, {%4,%5,%6,%7}, {%8,%9}, {%0,%1,%2,%3};"
                 : "+f"(c[0]), "+f"(c[1]), "+f"(c[2]), "+f"(c[3])
                 : "r"(a[0]), "r"(a[1]), "r"(a[2]), "r"(a[3]), "r"(b0), "r"(b1));
}

// smem geometry for GEMM1 operands (K-chunk = 32 bf16 = 64B data/row)
#define SROW_B   80                 // padded row pitch in bytes (conflict-free ldmatrix)
#define PLANE_B  10240              // 128 rows * 80B
#define BUF_B    40960              // 4 planes (A_hi, A_lo, B_hi, B_lo)

// =====================================================================
// Kernel A: LayerNorm + projections -> bf16 hi/lo planes (K-major)
// =====================================================================
__global__ __launch_bounds__(256) void ln_proj_kernel(
    const float* __restrict__ act, const float* __restrict__ mask,
    const float* __restrict__ ln_scale, const float* __restrict__ ln_offset,
    const float* __restrict__ lw, const float* __restrict__ lb,
    const float* __restrict__ rw, const float* __restrict__ rb)
{
    __shared__ float s_xn[C_M];
    __shared__ float s_red[16];
    const int row = blockIdx.x;       // row = a*N_RES + b
    const int tid = threadIdx.x;

    float x = act[row * C_M + tid];
    float s = x, s2 = x * x;
    #pragma unroll
    for (int o = 16; o; o >>= 1) {
        s  += __shfl_xor_sync(~0u, s,  o);
        s2 += __shfl_xor_sync(~0u, s2, o);
    }
    const int w = tid >> 5, l = tid & 31;
    if (l == 0) { s_red[w] = s; s_red[w + 8] = s2; }
    __syncthreads();
    if (tid == 0) {
        float ts = 0.f, ts2 = 0.f;
        #pragma unroll
        for (int i = 0; i < 8; i++) { ts += s_red[i]; ts2 += s_red[i + 8]; }
        float mu  = ts * (1.f / C_M);
        float var = ts2 * (1.f / C_M) - mu * mu;
        s_red[0] = mu;
        s_red[1] = rsqrtf(var + 1e-5f);
    }
    __syncthreads();
    const float mu = s_red[0], rstd = s_red[1];
    s_xn[tid] = (x - mu) * rstd * ln_scale[tid] + ln_offset[tid];
    __syncthreads();

    const int j = tid >> 2, q = tid & 3;
    const bool is_left = (j < C_OUTER);
    const float* W = is_left ? lw : rw;
    const int jj = j & (C_OUTER - 1);
    float acc = 0.f;
    const int mbase = q * 64;
    #pragma unroll 8
    for (int i = 0; i < 64; i++)
        acc += s_xn[mbase + i] * W[(mbase + i) * C_OUTER + jj];
    acc += __shfl_xor_sync(~0u, acc, 1);
    acc += __shfl_xor_sync(~0u, acc, 2);
    if (q == 0) {
        const float mv = mask[row];
        const float v = mv * (acc + (is_left ? lb[jj] : rb[jj]));
        const __nv_bfloat16 h = __float2bfloat16(v);
        const __nv_bfloat16 lo = __float2bfloat16(v - __bfloat162float(h));
        const int a = row / N_RES, b = row - a * N_RES;
        const size_t m = (size_t)b * C_OUTER + jj;
        __nv_bfloat16* dst = is_left ? g_A : g_B;
        dst[m * N_SEQ + a]         = h;
        dst[PLANE + m * N_SEQ + a] = lo;
    }
}

// =====================================================================
// Kernel B: norm[b,d] = sum_a mask[a,b]*mask[a,d]
// =====================================================================
__global__ void norm_kernel(const float* __restrict__ mask)
{
    const int d = blockIdx.x, b = threadIdx.x;
    float acc = 0.f;
    #pragma unroll 4
    for (int a = 0; a < N_SEQ; a++)
        acc += mask[a * N_RES + b] * mask[a * N_RES + d];
    g_norm[d * N_RES + b] = acc;
}

// =====================================================================
// Kernel C: HMMA bf16-split GEMM1 (128x128 tile over K=512, 3 hi/lo
// products into fp32 fragments) + SIMT f32x2 GEMM2 epilogue.
// grid=(96,96), 256 threads (8 warps of 64x32), 85504B dyn smem, 2 CTA/SM.
// =====================================================================
__global__ __launch_bounds__(256, 2)
void fused_tc_kernel(const float* __restrict__ ow, const float* __restrict__ ob,
                     float* __restrict__ out)
{
    extern __shared__ char sm_raw[];
    const uint32_t raw = smem_u32(sm_raw);
    const uint32_t base = (raw + 1023) & ~1023u;
    char* smc = sm_raw + (base - raw);
    float* smf = (float*)smc;

    const int tid = threadIdx.x;
    const int wid = tid >> 5, lane = tid & 31;
    const int bx = blockIdx.x, by = blockIdx.y;

    // ---------------- phase 1: GEMM1 via mma.sync ----------------
    // copy mapping: plane = tid>>6 (A_hi, A_lo, B_hi, B_lo); 2 rows/thread
    const int cp_plane = tid >> 6;
    const int cp_r0 = (tid & 63) * 2;
    const __nv_bfloat16* gplane;
    {
        const size_t Abase = (size_t)bx * 128 * N_SEQ;
        const size_t Bbase = (size_t)by * 128 * N_SEQ;
        gplane = (cp_plane < 2) ? (g_A + (cp_plane == 1 ? PLANE : 0) + Abase)
                                : (g_B + (cp_plane == 3 ? PLANE : 0) + Bbase);
    }
    const uint32_t cp_sbase = base + cp_plane * PLANE_B + cp_r0 * SROW_B;

    // ldmatrix per-lane byte offsets (within a buffer)
    const int wm = (wid >> 2) * 64;        // warp m-origin
    const int wn = (wid & 3) * 32;         // warp n-origin
    const uint32_t a_off = (uint32_t)(wm + (lane & 15)) * SROW_B + (lane >> 4) * 16;
    const uint32_t b_off = 2 * PLANE_B +
        (uint32_t)(wn + ((lane >> 4) << 3) + (lane & 7)) * SROW_B + ((lane >> 3) & 1) * 16;

    float acc[4][4][4];
    #pragma unroll
    for (int mt = 0; mt < 4; mt++)
        #pragma unroll
        for (int nt = 0; nt < 4; nt++)
            #pragma unroll
            for (int r = 0; r < 4; r++) acc[mt][nt][r] = 0.f;

    // prefetch chunk 0
    {
        #pragma unroll
        for (int rr = 0; rr < 2; rr++) {
            const char* g = (const char*)(gplane + (size_t)(cp_r0 + rr) * N_SEQ);
            const uint32_t sa = cp_sbase + rr * SROW_B;
            #pragma unroll
            for (int seg = 0; seg < 4; seg++) cp16(sa + seg * 16, g + seg * 16);
        }
        CP_COMMIT();
    }

    int bb = 0;
    for (int kc = 0; kc < 16; kc++) {
        if (kc < 15) {
            const int kn = (kc + 1) * 32;   // bf16 elements
            const uint32_t sb2 = cp_sbase + (bb ^ 1) * BUF_B;
            #pragma unroll
            for (int rr = 0; rr < 2; rr++) {
                const char* g = (const char*)(gplane + (size_t)(cp_r0 + rr) * N_SEQ + kn);
                const uint32_t sa = sb2 + rr * SROW_B;
                #pragma unroll
                for (int seg = 0; seg < 4; seg++) cp16(sa + seg * 16, g + seg * 16);
            }
            CP_COMMIT();
            CP_WAIT(1);
        } else {
            CP_WAIT(0);
        }
        __syncthreads();

        const uint32_t sb = base + bb * BUF_B;
        #pragma unroll
        for (int ks = 0; ks < 2; ks++) {
            const uint32_t ka = sb + a_off + ks * 32;
            const uint32_t kb = sb + b_off + ks * 32;
            uint32_t A4[4][4], B4[2][4], Bl[2][4];
            #pragma unroll
            for (int mt = 0; mt < 4; mt++) LDSM4(A4[mt], ka + mt * (16 * SROW_B));
            #pragma unroll
            for (int bt = 0; bt < 2; bt++) LDSM4(B4[bt], kb + bt * (16 * SROW_B));
            #pragma unroll
            for (int mt = 0; mt < 4; mt++)
                #pragma unroll
                for (int nt = 0; nt < 4; nt++)
                    mma16816(acc[mt][nt], A4[mt], B4[nt >> 1][(nt & 1) * 2],
                             B4[nt >> 1][(nt & 1) * 2 + 1]);
            #pragma unroll
            for (int bt = 0; bt < 2; bt++) LDSM4(Bl[bt], kb + PLANE_B + bt * (16 * SROW_B));
            #pragma unroll
            for (int mt = 0; mt < 4; mt++)
                #pragma unroll
                for (int nt = 0; nt < 4; nt++)
                    mma16816(acc[mt][nt], A4[mt], Bl[nt >> 1][(nt & 1) * 2],
                             Bl[nt >> 1][(nt & 1) * 2 + 1]);
            #pragma unroll
            for (int mt = 0; mt < 4; mt++) LDSM4(A4[mt], ka + PLANE_B + mt * (16 * SROW_B));
            #pragma unroll
            for (int mt = 0; mt < 4; mt++)
                #pragma unroll
                for (int nt = 0; nt < 4; nt++)
                    mma16816(acc[mt][nt], A4[mt], B4[nt >> 1][(nt & 1) * 2],
                             B4[nt >> 1][(nt & 1) * 2 + 1]);
        }
        __syncthreads();
        bb ^= 1;
    }

    // ---------------- spill fragments -> Cs [128][132] ----------------
    float* Cs = smf;
    float* Ws = smf + 16896;           // [32][132]
    {
        const int mr = wm + (lane >> 2);
        const int nc = wn + (lane & 3) * 2;
        #pragma unroll
        for (int mt = 0; mt < 4; mt++)
            #pragma unroll
            for (int nt = 0; nt < 4; nt++) {
                const int m = mr + mt * 16;
                const int n = nc + nt * 8;
                *(float2*)&Cs[m * 132 + n] =
                    make_float2(acc[mt][nt][0], acc[mt][nt][1]);
                *(float2*)&Cs[(m + 8) * 132 + n] =
                    make_float2(acc[mt][nt][2], acc[mt][nt][3]);
            }
    }

    // ---------------- phase 2: out = inter x W (SIMT f32x2) ----------------
    const int fg = lane & 15, kh = lane >> 4;
    const int p0 = wid * 2;
    const int bi0 = p0 >> 2, dj0 = p0 & 3;
    const int bi1 = (p0 + 1) >> 2, dj1 = (p0 + 1) & 3;
    const int rr = tid >> 3, cc = (tid & 7) * 16;    // W staging: 16 floats/thread
    const float4* ow4 = (const float4*)ow;

    ull o[2][4];
    #pragma unroll
    for (int p = 0; p < 2; p++)
        #pragma unroll
        for (int q = 0; q < 4; q++) o[p][q] = 0ull;

    float4 w4[4];
    #pragma unroll
    for (int q = 0; q < 4; q++)
        w4[q] = ow4[rr * 32 + (cc >> 2) + q];

    for (int ch = 0; ch < 32; ch++) {
        __syncthreads();            // Cs ready (first) / Ws free + prior compute done
        #pragma unroll
        for (int q = 0; q < 4; q++)
            *(float4*)&Ws[rr * 132 + cc + 4 * q] = w4[q];
        if (ch < 31) {
            #pragma unroll
            for (int q = 0; q < 4; q++)
                w4[q] = ow4[((ch + 1) * 32 + rr) * 32 + (cc >> 2) + q];
        }
        __syncthreads();            // Ws ready
        const float* c0 = Cs + (bi0 * 32 + ch) * 132 + dj0 * 32 + kh * 16;
        const float* c1 = Cs + (bi1 * 32 + ch) * 132 + dj1 * 32 + kh * 16;
        const float* wb = Ws + kh * 16 * 132 + fg * 8;
        #pragma unroll
        for (int j = 0; j < 16; j++) {
            const float s0 = c0[j], s1 = c1[j];
            const ulonglong2* wp = (const ulonglong2*)(wb + j * 132);
            const ulonglong2 wa = wp[0], wc = wp[1];
            const ull ps0 = pack2(s0, s0), ps1 = pack2(s1, s1);
            fma2(o[0][0], ps0, wa.x); fma2(o[0][1], ps0, wa.y);
            fma2(o[0][2], ps0, wc.x); fma2(o[0][3], ps0, wc.y);
            fma2(o[1][0], ps1, wa.x); fma2(o[1][1], ps1, wa.y);
            fma2(o[1][2], ps1, wc.x); fma2(o[1][3], ps1, wc.y);
        }
    }

    // reduce the two e-halves (FLOAT add on unpacked halves — NOT integer add)
    #pragma unroll
    for (int p = 0; p < 2; p++)
        #pragma unroll
        for (int q = 0; q < 4; q++) {
            const ull t = __shfl_xor_sync(~0u, o[p][q], 16);
            o[p][q] = pack2(lo2(o[p][q]) + lo2(t), hi2(o[p][q]) + hi2(t));
        }

    if (kh == 0) {
        const float4 bb0 = *(const float4*)&ob[fg * 8];
        const float4 bb1 = *(const float4*)&ob[fg * 8 + 4];
        #pragma unroll
        for (int p = 0; p < 2; p++) {
            const int bi = p ? bi1 : bi0, dj = p ? dj1 : dj0;
            const int b = bx * 4 + bi, d = by * 4 + dj;
            const float inv = 1.f / (1e-3f + g_norm[d * N_RES + b]);
            float4 r0, r1;
            r0.x = (lo2(o[p][0]) + bb0.x) * inv;
            r0.y = (hi2(o[p][0]) + bb0.y) * inv;
            r0.z = (lo2(o[p][1]) + bb0.z) * inv;
            r0.w = (hi2(o[p][1]) + bb0.w) * inv;
            r1.x = (lo2(o[p][2]) + bb1.x) * inv;
            r1.y = (hi2(o[p][2]) + bb1.y) * inv;
            r1.z = (lo2(o[p][3]) + bb1.z) * inv;
            r1.w = (hi2(o[p][3]) + bb1.w) * inv;
            float* op = out + ((size_t)b * N_RES + d) * C_Z + fg * 8;
            *(float4*)op = r0;
            *(float4*)(op + 4) = r1;
        }
    }
}

// =====================================================================
extern "C" void kernel_launch(void* const* d_in, const int* in_sizes, int n_in,
                              void* d_out, int out_size)
{
    (void)in_sizes; (void)n_in; (void)out_size;
    const float* act       = (const float*)d_in[0];
    const float* mask      = (const float*)d_in[1];
    const float* ln_scale  = (const float*)d_in[2];
    const float* ln_offset = (const float*)d_in[3];
    const float* left_w    = (const float*)d_in[4];
    const float* left_b    = (const float*)d_in[5];
    const float* right_w   = (const float*)d_in[6];
    const float* right_b   = (const float*)d_in[7];
    const float* output_w  = (const float*)d_in[8];
    const float* output_b  = (const float*)d_in[9];
    float* out = (float*)d_out;

    cudaFuncSetAttribute(fused_tc_kernel,
                         cudaFuncAttributeMaxDynamicSharedMemorySize, 85504);

    ln_proj_kernel<<<N_SEQ * N_RES, 256>>>(act, mask, ln_scale, ln_offset,
                                           left_w, left_b, right_w, right_b);
    norm_kernel<<<N_RES, N_RES>>>(mask);
    dim3 grid(96, 96);
    fused_tc_kernel<<<grid, 256, 85504>>>(output_w, output_b, out);
}

// round 14
// speedup vs baseline: 1.0919x; 1.0919x over previous
#include <cuda_runtime.h>
#include <cstdint>

#define N_SEQ 512
#define N_RES 384
#define C_M   256
#define C_OUTER 32
#define C_Z   128
#define M_DIM (N_RES * C_OUTER)   // 12288

typedef unsigned long long ull;

// scratch (device globals: allocation-free)
__device__ float g_left[N_SEQ * M_DIM];    // [a][m=b*32+c]
__device__ float g_right[N_SEQ * M_DIM];   // [a][m=d*32+e]
__device__ float g_norm[N_RES * N_RES];

// ---------- packed fp32x2 helpers ----------
__device__ __forceinline__ ull pack2(float x, float y) {
    ull r; asm("mov.b64 %0, {%1, %2};" : "=l"(r) : "f"(x), "f"(y)); return r;
}
__device__ __forceinline__ void fma2(ull& d, ull a, ull b) {
    asm("fma.rn.f32x2 %0, %1, %2, %3;" : "=l"(d) : "l"(a), "l"(b), "l"(d));
}
__device__ __forceinline__ float lo2(ull v) { return __uint_as_float((unsigned)v); }
__device__ __forceinline__ float hi2(ull v) { return __uint_as_float((unsigned)(v >> 32)); }

__device__ __forceinline__ uint32_t smem_u32(const void* p) {
    uint32_t a;
    asm("{ .reg .u64 t; cvta.to.shared.u64 t, %1; cvt.u32.u64 %0, t; }" : "=r"(a) : "l"(p));
    return a;
}
__device__ __forceinline__ void cp16(uint32_t s, const void* g) {
    asm volatile("cp.async.cg.shared.global [%0], [%1], 16;" :: "r"(s), "l"(g));
}
#define CP_COMMIT() asm volatile("cp.async.commit_group;" ::: "memory")
#define CP_WAIT0()  asm volatile("cp.async.wait_group 0;" ::: "memory")

// =====================================================================
// Kernel A: LayerNorm + left/right projections + mask, per (a,b) row.
// (proven-correct R5 version, unchanged)
// =====================================================================
__global__ __launch_bounds__(256) void ln_proj_kernel(
    const float* __restrict__ act, const float* __restrict__ mask,
    const float* __restrict__ ln_scale, const float* __restrict__ ln_offset,
    const float* __restrict__ lw, const float* __restrict__ lb,
    const float* __restrict__ rw, const float* __restrict__ rb)
{
    __shared__ float s_xn[C_M];
    __shared__ float s_red[16];
    const int row = blockIdx.x;
    const int tid = threadIdx.x;

    float x = act[row * C_M + tid];
    float s = x, s2 = x * x;
    #pragma unroll
    for (int o = 16; o; o >>= 1) {
        s  += __shfl_xor_sync(~0u, s,  o);
        s2 += __shfl_xor_sync(~0u, s2, o);
    }
    const int w = tid >> 5, l = tid & 31;
    if (l == 0) { s_red[w] = s; s_red[w + 8] = s2; }
    __syncthreads();
    if (tid == 0) {
        float ts = 0.f, ts2 = 0.f;
        #pragma unroll
        for (int i = 0; i < 8; i++) { ts += s_red[i]; ts2 += s_red[i + 8]; }
        float mu  = ts * (1.f / C_M);
        float var = ts2 * (1.f / C_M) - mu * mu;
        s_red[0] = mu;
        s_red[1] = rsqrtf(var + 1e-5f);
    }
    __syncthreads();
    const float mu = s_red[0], rstd = s_red[1];
    s_xn[tid] = (x - mu) * rstd * ln_scale[tid] + ln_offset[tid];
    __syncthreads();

    const int j = tid >> 2, q = tid & 3;
    const bool is_left = (j < C_OUTER);
    const float* W = is_left ? lw : rw;
    const int jj = j & (C_OUTER - 1);
    float acc = 0.f;
    const int mbase = q * 64;
    #pragma unroll 8
    for (int i = 0; i < 64; i++)
        acc += s_xn[mbase + i] * W[(mbase + i) * C_OUTER + jj];
    acc += __shfl_xor_sync(~0u, acc, 1);
    acc += __shfl_xor_sync(~0u, acc, 2);
    if (q == 0) {
        float mv = mask[row];
        float v = mv * (acc + (is_left ? lb[jj] : rb[jj]));
        if (is_left) g_left[row * C_OUTER + jj] = v;
        else         g_right[row * C_OUTER + jj] = v;
    }
}

// =====================================================================
// Kernel B: norm[b,d] = sum_a mask[a,b]*mask[a,d]
// =====================================================================
__global__ void norm_kernel(const float* __restrict__ mask)
{
    const int d = blockIdx.x, b = threadIdx.x;
    float acc = 0.f;
    #pragma unroll 4
    for (int a = 0; a < N_SEQ; a++)
        acc += mask[a * N_RES + b] * mask[a * N_RES + d];
    g_norm[d * N_RES + b] = acc;
}

// =====================================================================
// Kernel C: fused GEMM1 (R5-proven f32x2 SIMT, 128x128 tile, K=512)
// + NEW phase 2: 8-pair x 8-f mapping, conflict-free W vectors,
// cp.async 2-ch W staging, shfl + smem e-reduction.
// grid=(96,96), 256 threads, 100352B dyn smem, 2 CTAs/SM.
// =====================================================================
__global__ __launch_bounds__(256, 2) void fused_gemm_kernel(
    const float* __restrict__ ow, const float* __restrict__ ob,
    float* __restrict__ out)
{
    extern __shared__ float sm[];
    // phase1: As = sm[0..4095] (2 bufs x [16][128]); Bs = sm[4096..8191]
    // phase2: Cs = sm[0..16895] ([128][132]); Ws = sm[16896..25087] ([2][32][128])
    const int tid = threadIdx.x;
    const int wid = tid >> 5, lane = tid & 31;
    const int bx = blockIdx.x, by = blockIdx.y;
    const int m0 = bx * 128, n0 = by * 128;
    const int tr = tid >> 4, tc = tid & 15;     // 16x16 thread grid, 8x8 microtile
    const int r0 = tid >> 5;                    // 0..7 (global-load row)
    const int c4 = tid & 31;                    // float4 column

    float* Ws = sm + 16896;

    // prefetch W block 0 (Ws region untouched by phase 1 -> overlap for free)
    {
        const uint32_t wsa = smem_u32(Ws) + tid * 128;
        const float* src = ow + tid * 32;
        #pragma unroll
        for (int seg = 0; seg < 8; seg++) cp16(wsa + seg * 16, src + seg * 4);
        CP_COMMIT();
    }

    ull acc[8][4];
    #pragma unroll
    for (int i = 0; i < 8; i++)
        #pragma unroll
        for (int j = 0; j < 4; j++) acc[i][j] = 0ull;

    const float* A = g_left;
    const float* B = g_right;

    // preload chunk 0
    float4 na0 = *(const float4*)&A[(r0    ) * M_DIM + m0 + c4 * 4];
    float4 na1 = *(const float4*)&A[(r0 + 8) * M_DIM + m0 + c4 * 4];
    float4 nb0 = *(const float4*)&B[(r0    ) * M_DIM + n0 + c4 * 4];
    float4 nb1 = *(const float4*)&B[(r0 + 8) * M_DIM + n0 + c4 * 4];
    int buf = 0;
    *(float4*)&sm[buf * 2048 + (r0    ) * 128 + c4 * 4] = na0;
    *(float4*)&sm[buf * 2048 + (r0 + 8) * 128 + c4 * 4] = na1;
    *(float4*)&sm[4096 + buf * 2048 + (r0    ) * 128 + c4 * 4] = nb0;
    *(float4*)&sm[4096 + buf * 2048 + (r0 + 8) * 128 + c4 * 4] = nb1;
    __syncthreads();

    for (int kc = 0; kc < 32; kc++) {
        if (kc < 31) {
            const int k0n = (kc + 1) * 16;
            na0 = *(const float4*)&A[(k0n + r0    ) * M_DIM + m0 + c4 * 4];
            na1 = *(const float4*)&A[(k0n + r0 + 8) * M_DIM + m0 + c4 * 4];
            nb0 = *(const float4*)&B[(k0n + r0    ) * M_DIM + n0 + c4 * 4];
            nb1 = *(const float4*)&B[(k0n + r0 + 8) * M_DIM + n0 + c4 * 4];
        }
        const float* Asb = sm + buf * 2048;
        const float* Bsb = sm + 4096 + buf * 2048;
        #pragma unroll
        for (int k = 0; k < 16; k++) {
            float4 av0 = *(const float4*)&Asb[k * 128 + tr * 8];
            float4 av1 = *(const float4*)&Asb[k * 128 + tr * 8 + 4];
            const ull* bp = (const ull*)&Bsb[k * 128 + tc * 8];
            ull b2_0 = bp[0], b2_1 = bp[1], b2_2 = bp[2], b2_3 = bp[3];
            ull a2[8];
            a2[0] = pack2(av0.x, av0.x); a2[1] = pack2(av0.y, av0.y);
            a2[2] = pack2(av0.z, av0.z); a2[3] = pack2(av0.w, av0.w);
            a2[4] = pack2(av1.x, av1.x); a2[5] = pack2(av1.y, av1.y);
            a2[6] = pack2(av1.z, av1.z); a2[7] = pack2(av1.w, av1.w);
            #pragma unroll
            for (int i = 0; i < 8; i++) {
                fma2(acc[i][0], a2[i], b2_0);
                fma2(acc[i][1], a2[i], b2_1);
                fma2(acc[i][2], a2[i], b2_2);
                fma2(acc[i][3], a2[i], b2_3);
            }
        }
        if (kc < 31) {
            const int nb = buf ^ 1;
            *(float4*)&sm[nb * 2048 + (r0    ) * 128 + c4 * 4] = na0;
            *(float4*)&sm[nb * 2048 + (r0 + 8) * 128 + c4 * 4] = na1;
            *(float4*)&sm[4096 + nb * 2048 + (r0    ) * 128 + c4 * 4] = nb0;
            *(float4*)&sm[4096 + nb * 2048 + (r0 + 8) * 128 + c4 * 4] = nb1;
        }
        __syncthreads();
        buf ^= 1;
    }

    // ---------- spill GEMM1 accumulators -> Cs [128][132] ----------
    float* Cs = sm;
    #pragma unroll
    for (int i = 0; i < 8; i++) {
        const int rowb = (tr * 8 + i) * 132 + tc * 8;
        #pragma unroll
        for (int j = 0; j < 4; j++) *(ull*)&Cs[rowb + 2 * j] = acc[i][j];
    }

    // ---------- phase 2: out = inter x W ----------
    // warp: pair-group pg = wid&1 (pairs pg*8..+7), e-quarter eq = wid>>1
    // lane: fg = lane&15 -> f = fg*4 and 64+fg*4; eo = lane>>4 -> e offset
    const int fg = lane & 15, eo = lane >> 4;
    const int pg = wid & 1, eq = wid >> 1;
    const int ebase = eq * 8 + eo * 4;

    ull o[8][4];
    #pragma unroll
    for (int pp = 0; pp < 8; pp++)
        #pragma unroll
        for (int q = 0; q < 4; q++) o[pp][q] = 0ull;

    for (int chb = 0; chb < 16; chb++) {
        if (chb > 0) {
            __syncthreads();       // everyone finished reading Ws block chb-1
            const uint32_t wsa = smem_u32(Ws) + tid * 128;
            const float* src = ow + chb * 8192 + tid * 32;
            #pragma unroll
            for (int seg = 0; seg < 8; seg++) cp16(wsa + seg * 16, src + seg * 4);
            CP_COMMIT();
        }
        CP_WAIT0();
        __syncthreads();           // Ws (and, first time, Cs) visible to all
        #pragma unroll
        for (int cc = 0; cc < 2; cc++) {
            const int ch = chb * 2 + cc;
            const float* Wb = Ws + cc * 4096;
            #pragma unroll
            for (int j = 0; j < 4; j++) {
                const int e = ebase + j;
                float cv[8];
                #pragma unroll
                for (int pp = 0; pp < 8; pp++) {
                    const int p = pg * 8 + pp;
                    const int bi = p >> 2, dj = p & 3;
                    cv[pp] = Cs[(bi * 32 + ch) * 132 + dj * 32 + e];
                }
                const ulonglong2 wa = *(const ulonglong2*)&Wb[e * 128 + fg * 4];
                const ulonglong2 wc = *(const ulonglong2*)&Wb[e * 128 + 64 + fg * 4];
                #pragma unroll
                for (int pp = 0; pp < 8; pp++) {
                    const ull pc = pack2(cv[pp], cv[pp]);
                    fma2(o[pp][0], pc, wa.x); fma2(o[pp][1], pc, wa.y);
                    fma2(o[pp][2], pc, wc.x); fma2(o[pp][3], pc, wc.y);
                }
            }
        }
    }

    // intra-warp e-reduce (eo halves) — FLOAT adds on unpacked halves
    #pragma unroll
    for (int pp = 0; pp < 8; pp++)
        #pragma unroll
        for (int q = 0; q < 4; q++) {
            const ull t = __shfl_xor_sync(~0u, o[pp][q], 16);
            o[pp][q] = pack2(lo2(o[pp][q]) + lo2(t), hi2(o[pp][q]) + hi2(t));
        }

    __syncthreads();               // all compute done reading Cs; reuse it
    if (eq > 0 && lane < 16) {     // warps 2..7 park partials (stride 65: conflict-free)
        float* red = Cs + ((wid - 2) * 16 + lane) * 65;
        #pragma unroll
        for (int pp = 0; pp < 8; pp++)
            #pragma unroll
            for (int q = 0; q < 4; q++) {
                red[pp * 8 + 2 * q]     = lo2(o[pp][q]);
                red[pp * 8 + 2 * q + 1] = hi2(o[pp][q]);
            }
    }
    __syncthreads();

    if (eq == 0 && lane < 16) {    // warps 0,1 accumulate 3 partner quarters
        #pragma unroll
        for (int s = 0; s < 3; s++) {
            const float* red = Cs + ((s * 2 + pg) * 16 + lane) * 65;
            #pragma unroll
            for (int pp = 0; pp < 8; pp++)
                #pragma unroll
                for (int q = 0; q < 4; q++)
                    o[pp][q] = pack2(lo2(o[pp][q]) + red[pp * 8 + 2 * q],
                                     hi2(o[pp][q]) + red[pp * 8 + 2 * q + 1]);
        }

        const float4 bb0 = *(const float4*)&ob[fg * 4];
        const float4 bb1 = *(const float4*)&ob[64 + fg * 4];
        #pragma unroll
        for (int pp = 0; pp < 8; pp++) {
            const int p = pg * 8 + pp;
            const int bi = p >> 2, dj = p & 3;
            const int b = bx * 4 + bi, d = by * 4 + dj;
            const float inv = 1.f / (1e-3f + g_norm[d * N_RES + b]);
            float4 r0, r1;
            r0.x = (lo2(o[pp][0]) + bb0.x) * inv;
            r0.y = (hi2(o[pp][0]) + bb0.y) * inv;
            r0.z = (lo2(o[pp][1]) + bb0.z) * inv;
            r0.w = (hi2(o[pp][1]) + bb0.w) * inv;
            r1.x = (lo2(o[pp][2]) + bb1.x) * inv;
            r1.y = (hi2(o[pp][2]) + bb1.y) * inv;
            r1.z = (lo2(o[pp][3]) + bb1.z) * inv;
            r1.w = (hi2(o[pp][3]) + bb1.w) * inv;
            float* op = out + ((size_t)b * N_RES + d) * C_Z;
            *(float4*)(op + fg * 4)      = r0;
            *(float4*)(op + 64 + fg * 4) = r1;
        }
    }
}

// =====================================================================
extern "C" void kernel_launch(void* const* d_in, const int* in_sizes, int n_in,
                              void* d_out, int out_size)
{
    (void)in_sizes; (void)n_in; (void)out_size;
    const float* act       = (const float*)d_in[0];
    const float* mask      = (const float*)d_in[1];
    const float* ln_scale  = (const float*)d_in[2];
    const float* ln_offset = (const float*)d_in[3];
    const float* left_w    = (const float*)d_in[4];
    const float* left_b    = (const float*)d_in[5];
    const float* right_w   = (const float*)d_in[6];
    const float* right_b   = (const float*)d_in[7];
    const float* output_w  = (const float*)d_in[8];
    const float* output_b  = (const float*)d_in[9];
    float* out = (float*)d_out;

    cudaFuncSetAttribute(fused_gemm_kernel,
                         cudaFuncAttributeMaxDynamicSharedMemorySize, 100352);

    ln_proj_kernel<<<N_SEQ * N_RES, 256>>>(act, mask, ln_scale, ln_offset,
                                           left_w, left_b, right_w, right_b);
    norm_kernel<<<N_RES, N_RES>>>(mask);
    dim3 grid(96, 96);
    fused_gemm_kernel<<<grid, 256, 100352>>>(output_w, output_b, out);
}

// round 15
// speedup vs baseline: 1.1008x; 1.0082x over previous
#include <cuda_runtime.h>
#include <cstdint>

#define N_SEQ 512
#define N_RES 384
#define C_M   256
#define C_OUTER 32
#define C_Z   128
#define M_DIM (N_RES * C_OUTER)   // 12288

typedef unsigned long long ull;

// scratch (device globals: allocation-free)
__device__ float g_left[N_SEQ * M_DIM];    // [a][m=b*32+c]
__device__ float g_right[N_SEQ * M_DIM];   // [a][m=d*32+e]
__device__ float g_norm[N_RES * N_RES];

// ---------- packed fp32x2 helpers ----------
__device__ __forceinline__ ull pack2(float x, float y) {
    ull r; asm("mov.b64 %0, {%1, %2};" : "=l"(r) : "f"(x), "f"(y)); return r;
}
__device__ __forceinline__ void fma2(ull& d, ull a, ull b) {
    asm("fma.rn.f32x2 %0, %1, %2, %3;" : "=l"(d) : "l"(a), "l"(b), "l"(d));
}
__device__ __forceinline__ float lo2(ull v) { return __uint_as_float((unsigned)v); }
__device__ __forceinline__ float hi2(ull v) { return __uint_as_float((unsigned)(v >> 32)); }

__device__ __forceinline__ uint32_t smem_u32(const void* p) {
    uint32_t a;
    asm("{ .reg .u64 t; cvta.to.shared.u64 t, %1; cvt.u32.u64 %0, t; }" : "=r"(a) : "l"(p));
    return a;
}
__device__ __forceinline__ void cp16(uint32_t s, const void* g) {
    asm volatile("cp.async.cg.shared.global [%0], [%1], 16;" :: "r"(s), "l"(g));
}
#define CP_COMMIT() asm volatile("cp.async.commit_group;" ::: "memory")
#define CP_WAIT1()  asm volatile("cp.async.wait_group 1;" ::: "memory")
#define CP_WAIT0()  asm volatile("cp.async.wait_group 0;" ::: "memory")

// =====================================================================
// Kernel A: LayerNorm + projections (blocks < 196608) and
//           norm[b,d] = mask^T mask (blocks >= 196608).
// Merged so the fused kernel lands on ncu's -s 5 -c 1 capture slot.
// =====================================================================
__global__ __launch_bounds__(256) void ln_proj_kernel(
    const float* __restrict__ act, const float* __restrict__ mask,
    const float* __restrict__ ln_scale, const float* __restrict__ ln_offset,
    const float* __restrict__ lw, const float* __restrict__ lb,
    const float* __restrict__ rw, const float* __restrict__ rb)
{
    const int tid = threadIdx.x;

    if (blockIdx.x >= (N_SEQ * N_RES)) {          // ---- norm rows ----
        const int d = blockIdx.x - N_SEQ * N_RES;
        for (int b = tid; b < N_RES; b += 256) {
            float acc = 0.f;
            #pragma unroll 4
            for (int a = 0; a < N_SEQ; a++)
                acc += mask[a * N_RES + b] * mask[a * N_RES + d];
            g_norm[d * N_RES + b] = acc;
        }
        return;
    }

    __shared__ float s_xn[C_M];
    __shared__ float s_red[16];
    const int row = blockIdx.x;

    float x = act[row * C_M + tid];
    float s = x, s2 = x * x;
    #pragma unroll
    for (int o = 16; o; o >>= 1) {
        s  += __shfl_xor_sync(~0u, s,  o);
        s2 += __shfl_xor_sync(~0u, s2, o);
    }
    const int w = tid >> 5, l = tid & 31;
    if (l == 0) { s_red[w] = s; s_red[w + 8] = s2; }
    __syncthreads();
    if (tid == 0) {
        float ts = 0.f, ts2 = 0.f;
        #pragma unroll
        for (int i = 0; i < 8; i++) { ts += s_red[i]; ts2 += s_red[i + 8]; }
        float mu  = ts * (1.f / C_M);
        float var = ts2 * (1.f / C_M) - mu * mu;
        s_red[0] = mu;
        s_red[1] = rsqrtf(var + 1e-5f);
    }
    __syncthreads();
    const float mu = s_red[0], rstd = s_red[1];
    s_xn[tid] = (x - mu) * rstd * ln_scale[tid] + ln_offset[tid];
    __syncthreads();

    const int j = tid >> 2, q = tid & 3;
    const bool is_left = (j < C_OUTER);
    const float* W = is_left ? lw : rw;
    const int jj = j & (C_OUTER - 1);
    float acc = 0.f;
    const int mbase = q * 64;
    #pragma unroll 8
    for (int i = 0; i < 64; i++)
        acc += s_xn[mbase + i] * W[(mbase + i) * C_OUTER + jj];
    acc += __shfl_xor_sync(~0u, acc, 1);
    acc += __shfl_xor_sync(~0u, acc, 2);
    if (q == 0) {
        float mv = mask[row];
        float v = mv * (acc + (is_left ? lb[jj] : rb[jj]));
        if (is_left) g_left[row * C_OUTER + jj] = v;
        else         g_right[row * C_OUTER + jj] = v;
    }
}

// =====================================================================
// Kernel C: fused GEMM1 (f32x2 SIMT, 128x128 tile, K=512, 3-stage
// cp.async pipeline, 1 sync per chunk) + phase 2 (R14-proven).
// grid=(96,96), 256 threads, 100352B dyn smem, 2 CTAs/SM.
// =====================================================================
__global__ __launch_bounds__(256, 2) void fused_gemm_kernel(
    const float* __restrict__ ow, const float* __restrict__ ob,
    float* __restrict__ out)
{
    extern __shared__ float sm[];
    // phase1: 3 stages x [A(16x128) | B(16x128)] = 12288 floats (48KB)
    // phase2: Cs = sm[0..16895] ([128][132]); Ws = sm[16896..25087]
    const int tid = threadIdx.x;
    const int wid = tid >> 5, lane = tid & 31;
    const int bx = blockIdx.x, by = blockIdx.y;
    const int m0 = bx * 128, n0 = by * 128;
    const int tr = tid >> 4, tc = tid & 15;     // 16x16 thread grid, 8x8 microtile

    float* Ws = sm + 16896;
    const uint32_t sbase = smem_u32(sm);

    // prefetch W block 0 (group committed first; completes in order)
    {
        const uint32_t wsa = smem_u32(Ws) + tid * 128;
        const float* src = ow + tid * 32;
        #pragma unroll
        for (int seg = 0; seg < 8; seg++) cp16(wsa + seg * 16, src + seg * 4);
        CP_COMMIT();
    }

    // cp.async chunk issue: chunk j = K rows [j*16, j*16+16) of A and B
    // 1024 float4 per chunk, 4 per thread; stage j%3 at 16KB stride.
    const float* A = g_left;
    const float* B = g_right;
    // per-thread fixed mapping pieces
    const int idx0 = tid;            // seg stride 256

    ull acc[8][4];
    #pragma unroll
    for (int i = 0; i < 8; i++)
        #pragma unroll
        for (int j = 0; j < 4; j++) acc[i][j] = 0ull;

    // issue chunks 0 and 1
    #pragma unroll
    for (int j0 = 0; j0 < 2; j0++) {
        const uint32_t st = sbase + (j0 % 3) * 16384;
        #pragma unroll
        for (int seg = 0; seg < 4; seg++) {
            const int idx = seg * 256 + idx0;        // 0..1023
            const int op = idx >> 9;                 // 0=A, 1=B
            const int r = (idx >> 5) & 15, c = idx & 31;
            const float* g = (op ? B : A) + (size_t)(j0 * 16 + r) * M_DIM
                             + (op ? n0 : m0) + c * 4;
            cp16(st + (uint32_t)(op * 2048 + r * 128 + c * 4) * 4, g);
        }
        CP_COMMIT();
    }

    for (int kc = 0; kc < 32; kc++) {
        if (kc < 31) { CP_WAIT1(); } else { CP_WAIT0(); }
        __syncthreads();
        if (kc < 30) {
            const int jn = kc + 2;
            const uint32_t st = sbase + (jn % 3) * 16384;
            #pragma unroll
            for (int seg = 0; seg < 4; seg++) {
                const int idx = seg * 256 + idx0;
                const int op = idx >> 9;
                const int r = (idx >> 5) & 15, c = idx & 31;
                const float* g = (op ? B : A) + (size_t)(jn * 16 + r) * M_DIM
                                 + (op ? n0 : m0) + c * 4;
                cp16(st + (uint32_t)(op * 2048 + r * 128 + c * 4) * 4, g);
            }
            CP_COMMIT();
        }
        const float* Asb = sm + (kc % 3) * 4096;
        const float* Bsb = Asb + 2048;
        #pragma unroll
        for (int k = 0; k < 16; k++) {
            float4 av0 = *(const float4*)&Asb[k * 128 + tr * 8];
            float4 av1 = *(const float4*)&Asb[k * 128 + tr * 8 + 4];
            const ull* bp = (const ull*)&Bsb[k * 128 + tc * 8];
            ull b2_0 = bp[0], b2_1 = bp[1], b2_2 = bp[2], b2_3 = bp[3];
            ull a2[8];
            a2[0] = pack2(av0.x, av0.x); a2[1] = pack2(av0.y, av0.y);
            a2[2] = pack2(av0.z, av0.z); a2[3] = pack2(av0.w, av0.w);
            a2[4] = pack2(av1.x, av1.x); a2[5] = pack2(av1.y, av1.y);
            a2[6] = pack2(av1.z, av1.z); a2[7] = pack2(av1.w, av1.w);
            #pragma unroll
            for (int i = 0; i < 8; i++) {
                fma2(acc[i][0], a2[i], b2_0);
                fma2(acc[i][1], a2[i], b2_1);
                fma2(acc[i][2], a2[i], b2_2);
                fma2(acc[i][3], a2[i], b2_3);
            }
        }
    }
    __syncthreads();   // all reads of phase-1 smem done before Cs overwrite

    // ---------- spill GEMM1 accumulators -> Cs [128][132] ----------
    float* Cs = sm;
    #pragma unroll
    for (int i = 0; i < 8; i++) {
        const int rowb = (tr * 8 + i) * 132 + tc * 8;
        #pragma unroll
        for (int j = 0; j < 4; j++) *(ull*)&Cs[rowb + 2 * j] = acc[i][j];
    }

    // ---------- phase 2: out = inter x W (R14-proven mapping) ----------
    const int fg = lane & 15, eo = lane >> 4;
    const int pg = wid & 1, eq = wid >> 1;
    const int ebase = eq * 8 + eo * 4;

    ull o[8][4];
    #pragma unroll
    for (int pp = 0; pp < 8; pp++)
        #pragma unroll
        for (int q = 0; q < 4; q++) o[pp][q] = 0ull;

    for (int chb = 0; chb < 16; chb++) {
        if (chb > 0) {
            __syncthreads();       // everyone finished reading Ws block chb-1
            const uint32_t wsa = smem_u32(Ws) + tid * 128;
            const float* src = ow + chb * 8192 + tid * 32;
            #pragma unroll
            for (int seg = 0; seg < 8; seg++) cp16(wsa + seg * 16, src + seg * 4);
            CP_COMMIT();
        }
        CP_WAIT0();
        __syncthreads();           // Ws (and, first time, Cs) visible to all
        #pragma unroll
        for (int cc = 0; cc < 2; cc++) {
            const int ch = chb * 2 + cc;
            const float* Wb = Ws + cc * 4096;
            #pragma unroll
            for (int j = 0; j < 4; j++) {
                const int e = ebase + j;
                float cv[8];
                #pragma unroll
                for (int pp = 0; pp < 8; pp++) {
                    const int p = pg * 8 + pp;
                    const int bi = p >> 2, dj = p & 3;
                    cv[pp] = Cs[(bi * 32 + ch) * 132 + dj * 32 + e];
                }
                const ulonglong2 wa = *(const ulonglong2*)&Wb[e * 128 + fg * 4];
                const ulonglong2 wc = *(const ulonglong2*)&Wb[e * 128 + 64 + fg * 4];
                #pragma unroll
                for (int pp = 0; pp < 8; pp++) {
                    const ull pc = pack2(cv[pp], cv[pp]);
                    fma2(o[pp][0], pc, wa.x); fma2(o[pp][1], pc, wa.y);
                    fma2(o[pp][2], pc, wc.x); fma2(o[pp][3], pc, wc.y);
                }
            }
        }
    }

    // intra-warp e-reduce (eo halves) — FLOAT adds on unpacked halves
    #pragma unroll
    for (int pp = 0; pp < 8; pp++)
        #pragma unroll
        for (int q = 0; q < 4; q++) {
            const ull t = __shfl_xor_sync(~0u, o[pp][q], 16);
            o[pp][q] = pack2(lo2(o[pp][q]) + lo2(t), hi2(o[pp][q]) + hi2(t));
        }

    __syncthreads();               // all compute done reading Cs; reuse it
    if (eq > 0 && lane < 16) {     // warps 2..7 park partials (stride 65)
        float* red = Cs + ((wid - 2) * 16 + lane) * 65;
        #pragma unroll
        for (int pp = 0; pp < 8; pp++)
            #pragma unroll
            for (int q = 0; q < 4; q++) {
                red[pp * 8 + 2 * q]     = lo2(o[pp][q]);
                red[pp * 8 + 2 * q + 1] = hi2(o[pp][q]);
            }
    }
    __syncthreads();

    if (eq == 0 && lane < 16) {    // warps 0,1 accumulate 3 partner quarters
        #pragma unroll
        for (int s = 0; s < 3; s++) {
            const float* red = Cs + ((s * 2 + pg) * 16 + lane) * 65;
            #pragma unroll
            for (int pp = 0; pp < 8; pp++)
                #pragma unroll
                for (int q = 0; q < 4; q++)
                    o[pp][q] = pack2(lo2(o[pp][q]) + red[pp * 8 + 2 * q],
                                     hi2(o[pp][q]) + red[pp * 8 + 2 * q + 1]);
        }

        const float4 bb0 = *(const float4*)&ob[fg * 4];
        const float4 bb1 = *(const float4*)&ob[64 + fg * 4];
        #pragma unroll
        for (int pp = 0; pp < 8; pp++) {
            const int p = pg * 8 + pp;
            const int bi = p >> 2, dj = p & 3;
            const int b = bx * 4 + bi, d = by * 4 + dj;
            const float inv = 1.f / (1e-3f + g_norm[d * N_RES + b]);
            float4 r0, r1;
            r0.x = (lo2(o[pp][0]) + bb0.x) * inv;
            r0.y = (hi2(o[pp][0]) + bb0.y) * inv;
            r0.z = (lo2(o[pp][1]) + bb0.z) * inv;
            r0.w = (hi2(o[pp][1]) + bb0.w) * inv;
            r1.x = (lo2(o[pp][2]) + bb1.x) * inv;
            r1.y = (hi2(o[pp][2]) + bb1.y) * inv;
            r1.z = (lo2(o[pp][3]) + bb1.z) * inv;
            r1.w = (hi2(o[pp][3]) + bb1.w) * inv;
            float* op = out + ((size_t)b * N_RES + d) * C_Z;
            *(float4*)(op + fg * 4)      = r0;
            *(float4*)(op + 64 + fg * 4) = r1;
        }
    }
}

// =====================================================================
extern "C" void kernel_launch(void* const* d_in, const int* in_sizes, int n_in,
                              void* d_out, int out_size)
{
    (void)in_sizes; (void)n_in; (void)out_size;
    const float* act       = (const float*)d_in[0];
    const float* mask      = (const float*)d_in[1];
    const float* ln_scale  = (const float*)d_in[2];
    const float* ln_offset = (const float*)d_in[3];
    const float* left_w    = (const float*)d_in[4];
    const float* left_b    = (const float*)d_in[5];
    const float* right_w   = (const float*)d_in[6];
    const float* right_b   = (const float*)d_in[7];
    const float* output_w  = (const float*)d_in[8];
    const float* output_b  = (const float*)d_in[9];
    float* out = (float*)d_out;

    cudaFuncSetAttribute(fused_gemm_kernel,
                         cudaFuncAttributeMaxDynamicSharedMemorySize, 100352);

    // 2 launches per call -> ncu (-s 5 -c 1) captures the FUSED kernel
    ln_proj_kernel<<<N_SEQ * N_RES + N_RES, 256>>>(act, mask, ln_scale, ln_offset,
                                                   left_w, left_b, right_w, right_b);
    dim3 grid(96, 96);
    fused_gemm_kernel<<<grid, 256, 100352>>>(output_w, output_b, out);
}

// round 17
// speedup vs baseline: 1.1408x; 1.0363x over previous
#include <cuda_runtime.h>
#include <cstdint>

#define N_SEQ 512
#define N_RES 384
#define C_M   256
#define C_OUTER 32
#define C_Z   128
#define M_DIM (N_RES * C_OUTER)   // 12288

typedef unsigned long long ull;

// scratch (device globals: allocation-free)
__device__ float g_left[N_SEQ * M_DIM];    // [a][m=b*32+c]
__device__ float g_right[N_SEQ * M_DIM];   // [a][m=d*32+e]
__device__ float g_norm[N_RES * N_RES];

// ---------- packed fp32x2 helpers ----------
__device__ __forceinline__ ull pack2(float x, float y) {
    ull r; asm("mov.b64 %0, {%1, %2};" : "=l"(r) : "f"(x), "f"(y)); return r;
}
__device__ __forceinline__ void fma2(ull& d, ull a, ull b) {
    asm("fma.rn.f32x2 %0, %1, %2, %3;" : "=l"(d) : "l"(a), "l"(b), "l"(d));
}
__device__ __forceinline__ float lo2(ull v) { return __uint_as_float((unsigned)v); }
__device__ __forceinline__ float hi2(ull v) { return __uint_as_float((unsigned)(v >> 32)); }

__device__ __forceinline__ uint32_t smem_u32(const void* p) {
    uint32_t a;
    asm("{ .reg .u64 t; cvta.to.shared.u64 t, %1; cvt.u32.u64 %0, t; }" : "=r"(a) : "l"(p));
    return a;
}
__device__ __forceinline__ void cp16(uint32_t s, const void* g) {
    asm volatile("cp.async.cg.shared.global [%0], [%1], 16;" :: "r"(s), "l"(g));
}
#define CP_COMMIT() asm volatile("cp.async.commit_group;" ::: "memory")
#define CP_WAIT1()  asm volatile("cp.async.wait_group 1;" ::: "memory")
#define CP_WAIT0()  asm volatile("cp.async.wait_group 0;" ::: "memory")

// =====================================================================
// Kernel A: LayerNorm + projections (blocks < 196608) and
//           norm[b,d] = mask^T mask (blocks >= 196608). Unchanged.
// =====================================================================
__global__ __launch_bounds__(256) void ln_proj_kernel(
    const float* __restrict__ act, const float* __restrict__ mask,
    const float* __restrict__ ln_scale, const float* __restrict__ ln_offset,
    const float* __restrict__ lw, const float* __restrict__ lb,
    const float* __restrict__ rw, const float* __restrict__ rb)
{
    const int tid = threadIdx.x;

    if (blockIdx.x >= (N_SEQ * N_RES)) {          // ---- norm rows ----
        const int d = blockIdx.x - N_SEQ * N_RES;
        for (int b = tid; b < N_RES; b += 256) {
            float acc = 0.f;
            #pragma unroll 4
            for (int a = 0; a < N_SEQ; a++)
                acc += mask[a * N_RES + b] * mask[a * N_RES + d];
            g_norm[d * N_RES + b] = acc;
        }
        return;
    }

    __shared__ float s_xn[C_M];
    __shared__ float s_red[16];
    const int row = blockIdx.x;

    float x = act[row * C_M + tid];
    float s = x, s2 = x * x;
    #pragma unroll
    for (int o = 16; o; o >>= 1) {
        s  += __shfl_xor_sync(~0u, s,  o);
        s2 += __shfl_xor_sync(~0u, s2, o);
    }
    const int w = tid >> 5, l = tid & 31;
    if (l == 0) { s_red[w] = s; s_red[w + 8] = s2; }
    __syncthreads();
    if (tid == 0) {
        float ts = 0.f, ts2 = 0.f;
        #pragma unroll
        for (int i = 0; i < 8; i++) { ts += s_red[i]; ts2 += s_red[i + 8]; }
        float mu  = ts * (1.f / C_M);
        float var = ts2 * (1.f / C_M) - mu * mu;
        s_red[0] = mu;
        s_red[1] = rsqrtf(var + 1e-5f);
    }
    __syncthreads();
    const float mu = s_red[0], rstd = s_red[1];
    s_xn[tid] = (x - mu) * rstd * ln_scale[tid] + ln_offset[tid];
    __syncthreads();

    const int j = tid >> 2, q = tid & 3;
    const bool is_left = (j < C_OUTER);
    const float* W = is_left ? lw : rw;
    const int jj = j & (C_OUTER - 1);
    float acc = 0.f;
    const int mbase = q * 64;
    #pragma unroll 8
    for (int i = 0; i < 64; i++)
        acc += s_xn[mbase + i] * W[(mbase + i) * C_OUTER + jj];
    acc += __shfl_xor_sync(~0u, acc, 1);
    acc += __shfl_xor_sync(~0u, acc, 2);
    if (q == 0) {
        float mv = mask[row];
        float v = mv * (acc + (is_left ? lb[jj] : rb[jj]));
        if (is_left) g_left[row * C_OUTER + jj] = v;
        else         g_right[row * C_OUTER + jj] = v;
    }
}

// =====================================================================
// Kernel C: fused GEMM1+GEMM2. 512 threads, 8m x 4n microtile with
// m-paired f32x2 accumulators (A = warp broadcast, zero A-dup MOVs),
// 3-stage cp.async, 2 CTAs/SM => 32 warps/SM (50% occ).
// grid=(96,96), 100352B dyn smem.
// =====================================================================
__global__ __launch_bounds__(512, 2) void fused_gemm_kernel(
    const float* __restrict__ ow, const float* __restrict__ ob,
    float* __restrict__ out)
{
    extern __shared__ float sm[];
    // phase1: 3 stages x [A(16x128) | B(16x128)] = 12288 floats (48KB)
    // phase2: Cs = sm[0..16895] ([128][132]); Ws = sm[16896..25087]
    const int tid = threadIdx.x;
    const int wid = tid >> 5, lane = tid & 31;
    const int bx = blockIdx.x, by = blockIdx.y;
    const int m0 = bx * 128, n0 = by * 128;

    float* Ws = sm + 16896;
    const uint32_t sbase = smem_u32(sm);
    const uint32_t wbase = smem_u32(Ws);

    // prefetch W block 0 (first committed group; completes first)
    {
        const uint32_t wsa = wbase + tid * 64;
        const float* src = ow + tid * 16;
        #pragma unroll
        for (int seg = 0; seg < 4; seg++) cp16(wsa + seg * 16, src + seg * 4);
        CP_COMMIT();
    }

    const float* A = g_left;
    const float* B = g_right;

    // acc[mp][j]: lo <-> m = wid*8 + 2mp, hi <-> m = wid*8 + 2mp+1, n = lane*4 + j
    ull acc[4][4];
    #pragma unroll
    for (int i = 0; i < 4; i++)
        #pragma unroll
        for (int j = 0; j < 4; j++) acc[i][j] = 0ull;

    // issue chunks 0 and 1 (2 float4 per thread per chunk)
    #pragma unroll
    for (int j0 = 0; j0 < 2; j0++) {
        const uint32_t st = sbase + (j0 % 3) * 16384;
        #pragma unroll
        for (int seg = 0; seg < 2; seg++) {
            const int idx = seg * 512 + tid;          // 0..1023
            const int op = idx >> 9;                  // 0=A, 1=B
            const int r = (idx >> 5) & 15, c = idx & 31;
            const float* g = (op ? B : A) + (size_t)(j0 * 16 + r) * M_DIM
                             + (op ? n0 : m0) + c * 4;
            cp16(st + (uint32_t)(op * 2048 + r * 128 + c * 4) * 4, g);
        }
        CP_COMMIT();
    }

    for (int kc = 0; kc < 32; kc++) {
        if (kc < 31) { CP_WAIT1(); } else { CP_WAIT0(); }
        __syncthreads();
        if (kc < 30) {
            const int jn = kc + 2;
            const uint32_t st = sbase + (jn % 3) * 16384;
            #pragma unroll
            for (int seg = 0; seg < 2; seg++) {
                const int idx = seg * 512 + tid;
                const int op = idx >> 9;
                const int r = (idx >> 5) & 15, c = idx & 31;
                const float* g = (op ? B : A) + (size_t)(jn * 16 + r) * M_DIM
                                 + (op ? n0 : m0) + c * 4;
                cp16(st + (uint32_t)(op * 2048 + r * 128 + c * 4) * 4, g);
            }
            CP_COMMIT();
        }
        const float* Asb = sm + (kc % 3) * 4096;
        const float* Bsb = Asb + 2048;
        #pragma unroll
        for (int k = 0; k < 16; k++) {
            const ull* ap = (const ull*)&Asb[k * 128 + wid * 8];   // warp broadcast
            const ull a0 = ap[0], a1 = ap[1], a2 = ap[2], a3 = ap[3];
            const float4 bv = *(const float4*)&Bsb[k * 128 + lane * 4];
            const ull b0 = pack2(bv.x, bv.x), b1 = pack2(bv.y, bv.y);
            const ull b2 = pack2(bv.z, bv.z), b3 = pack2(bv.w, bv.w);
            fma2(acc[0][0], a0, b0); fma2(acc[0][1], a0, b1);
            fma2(acc[0][2], a0, b2); fma2(acc[0][3], a0, b3);
            fma2(acc[1][0], a1, b0); fma2(acc[1][1], a1, b1);
            fma2(acc[1][2], a1, b2); fma2(acc[1][3], a1, b3);
            fma2(acc[2][0], a2, b0); fma2(acc[2][1], a2, b1);
            fma2(acc[2][2], a2, b2); fma2(acc[2][3], a2, b3);
            fma2(acc[3][0], a3, b0); fma2(acc[3][1], a3, b1);
            fma2(acc[3][2], a3, b2); fma2(acc[3][3], a3, b3);
        }
    }
    __syncthreads();   // all reads of phase-1 smem done before Cs overwrite

    // ---------- spill GEMM1 accumulators -> Cs [128][132] ----------
    float* Cs = sm;
    #pragma unroll
    for (int mp = 0; mp < 4; mp++) {
        const int r0 = (wid * 8 + 2 * mp) * 132 + lane * 4;
        #pragma unroll
        for (int j = 0; j < 4; j++) {
            Cs[r0 + j]       = lo2(acc[mp][j]);
            Cs[r0 + 132 + j] = hi2(acc[mp][j]);
        }
    }

    // ---------- phase 2: out = inter x W ----------
    // warp: pg = wid&1 -> pairs pg*8..+7 ; eq = wid>>1 -> e slice eq*4..+3
    // lane: f = lane*4 .. +3 (one float4 of f per lane)
    const int pg = wid & 1, eq = wid >> 1;
    const int f0 = lane * 4;

    ull o[8][2];
    #pragma unroll
    for (int pp = 0; pp < 8; pp++) { o[pp][0] = 0ull; o[pp][1] = 0ull; }

    for (int chb = 0; chb < 16; chb++) {
        if (chb > 0) {
            __syncthreads();       // everyone finished reading Ws block chb-1
            const uint32_t wsa = wbase + tid * 64;
            const float* src = ow + chb * 8192 + tid * 16;
            #pragma unroll
            for (int seg = 0; seg < 4; seg++) cp16(wsa + seg * 16, src + seg * 4);
            CP_COMMIT();
        }
        CP_WAIT0();
        __syncthreads();           // Ws (and, first time, Cs) visible to all
        #pragma unroll
        for (int cc = 0; cc < 2; cc++) {
            const int ch = chb * 2 + cc;
            const float* Wb = Ws + cc * 4096;
            // cv4[pp]: 4 consecutive e values (warp-broadcast float4)
            float4 cv4[8];
            #pragma unroll
            for (int pp = 0; pp < 8; pp++) {
                const int p = pg * 8 + pp;
                const int bi = p >> 2, dj = p & 3;
                cv4[pp] = *(const float4*)&Cs[(bi * 32 + ch) * 132 + dj * 32 + eq * 4];
            }
            #pragma unroll
            for (int j = 0; j < 4; j++) {
                const int e = eq * 4 + j;
                const ulonglong2 wv = *(const ulonglong2*)&Wb[e * 128 + f0];
                #pragma unroll
                for (int pp = 0; pp < 8; pp++) {
                    const float cvs = j == 0 ? cv4[pp].x : j == 1 ? cv4[pp].y
                                     : j == 2 ? cv4[pp].z : cv4[pp].w;
                    const ull pc = pack2(cvs, cvs);
                    fma2(o[pp][0], pc, wv.x);
                    fma2(o[pp][1], pc, wv.y);
                }
            }
        }
    }

    // ---------- e-reduction across the 8 eq slices (via smem) ----------
    __syncthreads();               // all compute done reading Cs; reuse it
    if (eq > 0) {                  // warps 2..15 park partials (stride 17 ull)
        ull* red = (ull*)Cs + ((size_t)(wid - 2) * 32 + lane) * 17;
        #pragma unroll
        for (int pp = 0; pp < 8; pp++) {
            red[pp * 2]     = o[pp][0];
            red[pp * 2 + 1] = o[pp][1];
        }
    }
    __syncthreads();

    if (eq == 0) {                 // warps 0,1 accumulate 7 partner slices
        #pragma unroll
        for (int s = 0; s < 7; s++) {
            const ull* red = (const ull*)Cs + ((size_t)(s * 2 + pg) * 32 + lane) * 17;
            #pragma unroll
            for (int pp = 0; pp < 8; pp++) {
                const ull t0 = red[pp * 2], t1 = red[pp * 2 + 1];
                o[pp][0] = pack2(lo2(o[pp][0]) + lo2(t0), hi2(o[pp][0]) + hi2(t0));
                o[pp][1] = pack2(lo2(o[pp][1]) + lo2(t1), hi2(o[pp][1]) + hi2(t1));
            }
        }

        const float4 bb = *(const float4*)&ob[f0];
        #pragma unroll
        for (int pp = 0; pp < 8; pp++) {
            const int p = pg * 8 + pp;
            const int bi = p >> 2, dj = p & 3;
            const int b = bx * 4 + bi, d = by * 4 + dj;
            const float inv = 1.f / (1e-3f + g_norm[d * N_RES + b]);
            float4 r;
            r.x = (lo2(o[pp][0]) + bb.x) * inv;
            r.y = (hi2(o[pp][0]) + bb.y) * inv;
            r.z = (lo2(o[pp][1]) + bb.z) * inv;
            r.w = (hi2(o[pp][1]) + bb.w) * inv;
            *(float4*)&out[((size_t)b * N_RES + d) * C_Z + f0] = r;
        }
    }
}

// =====================================================================
extern "C" void kernel_launch(void* const* d_in, const int* in_sizes, int n_in,
                              void* d_out, int out_size)
{
    (void)in_sizes; (void)n_in; (void)out_size;
    const float* act       = (const float*)d_in[0];
    const float* mask      = (const float*)d_in[1];
    const float* ln_scale  = (const float*)d_in[2];
    const float* ln_offset = (const float*)d_in[3];
    const float* left_w    = (const float*)d_in[4];
    const float* left_b    = (const float*)d_in[5];
    const float* right_w   = (const float*)d_in[6];
    const float* right_b   = (const float*)d_in[7];
    const float* output_w  = (const float*)d_in[8];
    const float* output_b  = (const float*)d_in[9];
    float* out = (float*)d_out;

    cudaFuncSetAttribute(fused_gemm_kernel,
                         cudaFuncAttributeMaxDynamicSharedMemorySize, 100352);

    // 2 launches per call -> ncu (-s 5 -c 1) captures the FUSED kernel
    ln_proj_kernel<<<N_SEQ * N_RES + N_RES, 256>>>(act, mask, ln_scale, ln_offset,
                                                   left_w, left_b, right_w, right_b);
    dim3 grid(96, 96);
    fused_gemm_kernel<<<grid, 512, 100352>>>(output_w, output_b, out);
}